// round 8
// baseline (speedup 1.0000x reference)
#include <cuda_runtime.h>
#include <math.h>
#include <stdint.h>

#define N_NODES 50000
#define IN_DIM  27
#define F1      256
#define H1      4
#define F2      128
#define H2      2
#define MAX_ET  400000

// ---------------- scratch (no allocations allowed) ----------------
__device__ float g_h1  [N_NODES * F1];
__device__ float g_agg1[N_NODES * F1];
__device__ float g_h2  [N_NODES * F2];
__device__ float g_agg2[N_NODES * F2];
__device__ float g_ss  [N_NODES * H1];
__device__ float g_sd  [N_NODES * H1];
__device__ float g_z   [N_NODES * H1];
__device__ int   g_deg [N_NODES];
__device__ int   g_rowp[N_NODES];
__device__ int   g_curs[N_NODES];
__device__ int   g_col [MAX_ET];

__device__ __forceinline__ float elu_fast(float v) {
    return (v > 0.f) ? v : (__expf(v) - 1.f);
}

// packed f32x2 helpers (plain sm_100+ PTX feature, not an 'a' feature)
__device__ __forceinline__ unsigned long long rep2(float x) {
    unsigned long long r;
    asm("mov.b64 %0, {%1, %1};" : "=l"(r) : "f"(x));
    return r;
}
#define FMA2(d, a, b) \
    asm("fma.rn.f32x2 %0, %1, %2, %0;" : "+l"(d) : "l"(a), "l"(b))

// ---------------- GEMM1: x[N,27] @ W1[27,256] -> h1[N,256] ----------------
__global__ void gemm1_kernel(const float* __restrict__ x,
                             const float* __restrict__ W,
                             float* __restrict__ out) {
    __shared__ float Ws[IN_DIM * F1];
    __shared__ float xs[64 * IN_DIM];
    int t = threadIdx.x;                // 256 threads
    for (int i = t; i < IN_DIM * F1; i += 256) Ws[i] = W[i];
    int r0 = blockIdx.x * 64;
    for (int i = t; i < 64 * IN_DIM; i += 256) {
        int r = i / IN_DIM, c = i % IN_DIM;
        int gr = r0 + r;
        xs[i] = (gr < N_NODES) ? x[gr * IN_DIM + c] : 0.f;
    }
    __syncthreads();
    float w[IN_DIM];
#pragma unroll
    for (int k = 0; k < IN_DIM; k++) w[k] = Ws[k * F1 + t];
    for (int r = 0; r < 64; r++) {
        int gr = r0 + r;
        if (gr >= N_NODES) break;
        float acc = 0.f;
#pragma unroll
        for (int k = 0; k < IN_DIM; k++) acc += xs[r * IN_DIM + k] * w[k];
        out[(size_t)gr * F1 + t] = acc;
    }
}

// ---------------- per-node attention half-scores ----------------
template<int H>
__global__ void scores_kernel(const float* __restrict__ h,
                              const float* __restrict__ asrc,
                              const float* __restrict__ adst,
                              float* __restrict__ ss, float* __restrict__ sd) {
    int gid  = blockIdx.x * blockDim.x + threadIdx.x;
    int warp = gid >> 5, lane = gid & 31;
    if (warp >= N_NODES * H) return;
    int n = warp / H, hh = warp % H;
    const float* hp = h + (size_t)n * (H * 64) + hh * 64;
    const float* as = asrc + hh * 64;
    const float* ad = adst + hh * 64;
    float v0 = hp[lane], v1 = hp[lane + 32];
    float s1 = v0 * as[lane] + v1 * as[lane + 32];
    float s2 = v0 * ad[lane] + v1 * ad[lane + 32];
#pragma unroll
    for (int o = 16; o > 0; o >>= 1) {
        s1 += __shfl_down_sync(0xffffffffu, s1, o);
        s2 += __shfl_down_sync(0xffffffffu, s2, o);
    }
    if (lane == 0) { ss[warp] = s1; sd[warp] = s2; }
}

// ---------------- CSR build: histogram, scan, scatter ----------------
__global__ void hist_kernel(const int* __restrict__ ei, int E, int ET,
                            int* __restrict__ deg) {
    int e = blockIdx.x * blockDim.x + threadIdx.x;
    if (e >= ET) return;
    int dst = (e < E) ? ei[E + e] : (e - E);
    atomicAdd(&deg[dst], 1);
}

__global__ void scan_kernel(const int* __restrict__ deg,
                            int* __restrict__ rowp, int* __restrict__ curs) {
    __shared__ int sums[1024];
    int t = threadIdx.x;                      // 1024 threads, 1 block
    const int CH = (N_NODES + 1023) / 1024;   // 49
    int beg = t * CH, end = min(beg + CH, N_NODES);
    int s = 0;
    for (int i = beg; i < end; i++) s += deg[i];
    sums[t] = s;
    __syncthreads();
    for (int off = 1; off < 1024; off <<= 1) {
        int v = (t >= off) ? sums[t - off] : 0;
        __syncthreads();
        sums[t] += v;
        __syncthreads();
    }
    int base = (t == 0) ? 0 : sums[t - 1];
    for (int i = beg; i < end; i++) {
        rowp[i] = base; curs[i] = base; base += deg[i];
    }
}

__global__ void scatter_kernel(const int* __restrict__ ei, int E, int ET,
                               int* __restrict__ curs, int* __restrict__ col) {
    int e = blockIdx.x * blockDim.x + threadIdx.x;
    if (e >= ET) return;
    int src, dst;
    if (e < E) { src = ei[e]; dst = ei[E + e]; }
    else       { src = dst = e - E; }
    int pos = atomicAdd(&curs[dst], 1);
    col[pos] = src;
}

// ---------------- CSR aggregation: one warp per destination node.
// z[n,h] = sum_e exp(lrelu(ss[src]+sd[n])); agg[n] = sum_e e*h[src]. No atomics. ----------------
template<int H, int F>
__global__ void edge_agg_csr(const int* __restrict__ rowp,
                             const int* __restrict__ deg,
                             const int* __restrict__ col,
                             const float* __restrict__ ss,
                             const float* __restrict__ sd,
                             float* __restrict__ z,
                             const float* __restrict__ h,
                             float* __restrict__ agg) {
    int gid = blockIdx.x * blockDim.x + threadIdx.x;
    int n = gid >> 5, lane = gid & 31;
    if (n >= N_NODES) return;
    int beg = rowp[n], d = deg[n];
    int h0 = lane >> 4;                       // head of float4 index f0 = lane
    int h1i = (lane + 32) >> 4;               // head of f1 = lane+32 (F==256 only)
    float sd0 = sd[n * H + h0];
    float sd1 = (F == 256) ? sd[n * H + h1i] : 0.f;
    float4 a0 = make_float4(0.f, 0.f, 0.f, 0.f);
    float4 a1 = make_float4(0.f, 0.f, 0.f, 0.f);
    float z0 = 0.f, z1 = 0.f;                 // accumulated on lanes 0 and 16
    for (int j = 0; j < d; j++) {
        int src = col[beg + j];
        const float4* hs = (const float4*)(h + (size_t)src * F);
        float l0 = ss[src * H + h0] + sd0;
        l0 = (l0 > 0.f) ? l0 : 0.2f * l0;
        float e0 = __expf(l0);
        float4 v0 = hs[lane];
        a0.x = fmaf(e0, v0.x, a0.x); a0.y = fmaf(e0, v0.y, a0.y);
        a0.z = fmaf(e0, v0.z, a0.z); a0.w = fmaf(e0, v0.w, a0.w);
        if (F == 256) {
            float l1 = ss[src * H + h1i] + sd1;
            l1 = (l1 > 0.f) ? l1 : 0.2f * l1;
            float e1 = __expf(l1);
            float4 v1 = hs[lane + 32];
            a1.x = fmaf(e1, v1.x, a1.x); a1.y = fmaf(e1, v1.y, a1.y);
            a1.z = fmaf(e1, v1.z, a1.z); a1.w = fmaf(e1, v1.w, a1.w);
            if (lane == 0 || lane == 16) { z0 += e0; z1 += e1; }
        } else {
            if (lane == 0 || lane == 16) z0 += e0;
        }
    }
    float4* ag = (float4*)(agg + (size_t)n * F);
    ag[lane] = a0;
    if (F == 256) {
        ag[lane + 32] = a1;
        if (lane == 0)  { z[n * 4 + 0] = z0; z[n * 4 + 2] = z1; }
        if (lane == 16) { z[n * 4 + 1] = z0; z[n * 4 + 3] = z1; }
    } else {
        if (lane == 0)  z[n * 2 + 0] = z0;
        if (lane == 16) z[n * 2 + 1] = z0;
    }
}

// ---------------- GEMM2 (f32x2 SIMT, double-buffered A, resident B) with FUSED
// layer-1 finalize on A-load: A_eff = elu(agg1/(z1+eps)+b1); C = A_eff @ W2 ----------------
// smem: Bs fp32 [256][128] (131072B) + As2 f32x2-replicated [2][16][132] (33792B)
#define G2_SMEM_B   0
#define G2_SMEM_A   131072
#define G2_SMEM_TOT (131072 + 2 * 16 * 132 * 8)

__global__ void __launch_bounds__(256, 1)
gemm2_db_kernel(const float* __restrict__ A,
                const float* __restrict__ zA,
                const float* __restrict__ bA,
                const float* __restrict__ B,
                float* __restrict__ C) {
    extern __shared__ char smem[];
    float* Bs = (float*)(smem + G2_SMEM_B);
    unsigned long long* As2 = (unsigned long long*)(smem + G2_SMEM_A);
    const unsigned long long* Bs2 = (const unsigned long long*)Bs;

    int t = threadIdx.x;            // 256 threads
    int tx = t & 15, ty = t >> 4;
    int row0 = blockIdx.x * 128;

    // resident B: copy all of W2 (256x128 fp32 = 128KB), linear
    {
        const float4* src = (const float4*)B;
        float4* dst = (float4*)Bs;
#pragma unroll
        for (int s = 0; s < 32; s++) dst[t + s * 256] = src[t + s * 256];
    }

    unsigned long long acc[8][4];
#pragma unroll
    for (int i = 0; i < 8; i++)
#pragma unroll
        for (int q = 0; q < 4; q++) acc[i][q] = 0ULL;

    // per-thread staging coords: idx = t + s*256 -> r = idx>>2, kq = idx&3
    int r_[2], kq_[2], gr_[2];
#pragma unroll
    for (int s = 0; s < 2; s++) {
        int idx = t + s * 256;
        r_[s] = idx >> 2; kq_[s] = idx & 3;
        gr_[s] = row0 + r_[s];
    }

    float4 g[2], bb[2];
    float  rz[2];

    // prefetch tile 0
#pragma unroll
    for (int s = 0; s < 2; s++) {
        int c = kq_[s] * 4;
        if (gr_[s] < N_NODES) {
            g[s]  = *(const float4*)&A[(size_t)gr_[s] * 256 + c];
            bb[s] = *(const float4*)&bA[c];
            rz[s] = __fdividef(1.f, zA[gr_[s] * H1 + (c >> 6)] + 1e-16f);
        }
    }
    // transform + store tile 0 into buf 0
#pragma unroll
    for (int s = 0; s < 2; s++) {
        float4 v = make_float4(0.f, 0.f, 0.f, 0.f);
        if (gr_[s] < N_NODES) {
            v.x = elu_fast(fmaf(g[s].x, rz[s], bb[s].x));
            v.y = elu_fast(fmaf(g[s].y, rz[s], bb[s].y));
            v.z = elu_fast(fmaf(g[s].z, rz[s], bb[s].z));
            v.w = elu_fast(fmaf(g[s].w, rz[s], bb[s].w));
        }
        unsigned long long* dst = As2 + (kq_[s] * 4) * 132 + r_[s];
        dst[0 * 132] = rep2(v.x); dst[1 * 132] = rep2(v.y);
        dst[2 * 132] = rep2(v.z); dst[3 * 132] = rep2(v.w);
    }
    __syncthreads();

    for (int kt = 0; kt < 16; kt++) {
        // prefetch next tile while computing this one
        if (kt < 15) {
#pragma unroll
            for (int s = 0; s < 2; s++) {
                int c = (kt + 1) * 16 + kq_[s] * 4;
                if (gr_[s] < N_NODES) {
                    g[s]  = *(const float4*)&A[(size_t)gr_[s] * 256 + c];
                    bb[s] = *(const float4*)&bA[c];
                    rz[s] = __fdividef(1.f, zA[gr_[s] * H1 + (c >> 6)] + 1e-16f);
                }
            }
        }
        // compute from buffer kt&1
        const unsigned long long* A2 = As2 + (kt & 1) * (16 * 132);
#pragma unroll
        for (int k = 0; k < 16; k++) {
            unsigned long long a2[8], b2[4];
#pragma unroll
            for (int i = 0; i < 8; i++) a2[i] = A2[k * 132 + ty * 8 + i];
#pragma unroll
            for (int q = 0; q < 4; q++)
                b2[q] = Bs2[(kt * 16 + k) * 64 + tx + q * 16];
#pragma unroll
            for (int i = 0; i < 8; i++)
#pragma unroll
                for (int q = 0; q < 4; q++)
                    FMA2(acc[i][q], a2[i], b2[q]);
        }
        // transform + store next tile into buffer (kt+1)&1
        if (kt < 15) {
            unsigned long long* dstbuf = As2 + ((kt + 1) & 1) * (16 * 132);
#pragma unroll
            for (int s = 0; s < 2; s++) {
                float4 v = make_float4(0.f, 0.f, 0.f, 0.f);
                if (gr_[s] < N_NODES) {
                    v.x = elu_fast(fmaf(g[s].x, rz[s], bb[s].x));
                    v.y = elu_fast(fmaf(g[s].y, rz[s], bb[s].y));
                    v.z = elu_fast(fmaf(g[s].z, rz[s], bb[s].z));
                    v.w = elu_fast(fmaf(g[s].w, rz[s], bb[s].w));
                }
                unsigned long long* dst = dstbuf + (kq_[s] * 4) * 132 + r_[s];
                dst[0 * 132] = rep2(v.x); dst[1 * 132] = rep2(v.y);
                dst[2 * 132] = rep2(v.z); dst[3 * 132] = rep2(v.w);
            }
            __syncthreads();
        }
    }

    // writeback: thread owns rows row0+ty*8+i, column pairs p = tx+16q -> cols 2p,2p+1
#pragma unroll
    for (int i = 0; i < 8; i++) {
        int gr = row0 + ty * 8 + i;
        if (gr >= N_NODES) continue;
#pragma unroll
        for (int q = 0; q < 4; q++)
            *(unsigned long long*)&C[(size_t)gr * 128 + 2 * (tx + 16 * q)] = acc[i][q];
    }
}

// ---------------- final (FUSED layer-2 finalize):
// out = sigmoid( elu(agg2/(z2+eps)+b2) @ Wfc + bfc ) ----------------
__global__ void out_fused_kernel(const float* __restrict__ agg,
                                 const float* __restrict__ z,
                                 const float* __restrict__ b,
                                 const float* __restrict__ Wfc,
                                 const float* __restrict__ bfc,
                                 float* __restrict__ out) {
    int gid = blockIdx.x * blockDim.x + threadIdx.x;
    int n = gid >> 5, lane = gid & 31;
    if (n >= N_NODES) return;
    const float* hp = agg + (size_t)n * 128;
    float rz0 = __fdividef(1.f, z[n * H2 + 0] + 1e-16f);
    float rz1 = __fdividef(1.f, z[n * H2 + 1] + 1e-16f);
    float v0 = elu_fast(fmaf(hp[lane],      rz0, b[lane]));
    float v1 = elu_fast(fmaf(hp[lane + 32], rz0, b[lane + 32]));
    float v2 = elu_fast(fmaf(hp[lane + 64], rz1, b[lane + 64]));
    float v3 = elu_fast(fmaf(hp[lane + 96], rz1, b[lane + 96]));
    float s = v0 * Wfc[lane] + v1 * Wfc[lane + 32]
            + v2 * Wfc[lane + 64] + v3 * Wfc[lane + 96];
#pragma unroll
    for (int o = 16; o > 0; o >>= 1) s += __shfl_down_sync(0xffffffffu, s, o);
    if (lane == 0) {
        float v = s + bfc[0];
        out[n] = 1.f / (1.f + __expf(-v));
    }
}

// ---------------- launch ----------------
extern "C" void kernel_launch(void* const* d_in, const int* in_sizes, int n_in,
                              void* d_out, int out_size) {
    const float* x      = (const float*)d_in[0];
    const int*   ei     = (const int*)  d_in[1];
    const float* W1     = (const float*)d_in[2];
    const float* a_src1 = (const float*)d_in[3];
    const float* a_dst1 = (const float*)d_in[4];
    const float* b1     = (const float*)d_in[5];
    const float* W2     = (const float*)d_in[6];
    const float* a_src2 = (const float*)d_in[7];
    const float* a_dst2 = (const float*)d_in[8];
    const float* b2     = (const float*)d_in[9];
    const float* Wfc    = (const float*)d_in[10];
    const float* bfc    = (const float*)d_in[11];
    float* out = (float*)d_out;

    int E  = in_sizes[1] / 2;
    int ET = E + N_NODES;

    float *h1, *agg1, *h2, *agg2, *ss, *sd, *z;
    int *deg, *rowp, *curs, *col;
    cudaGetSymbolAddress((void**)&h1,   g_h1);
    cudaGetSymbolAddress((void**)&agg1, g_agg1);
    cudaGetSymbolAddress((void**)&h2,   g_h2);
    cudaGetSymbolAddress((void**)&agg2, g_agg2);
    cudaGetSymbolAddress((void**)&ss,   g_ss);
    cudaGetSymbolAddress((void**)&sd,   g_sd);
    cudaGetSymbolAddress((void**)&z,    g_z);
    cudaGetSymbolAddress((void**)&deg,  g_deg);
    cudaGetSymbolAddress((void**)&rowp, g_rowp);
    cudaGetSymbolAddress((void**)&curs, g_curs);
    cudaGetSymbolAddress((void**)&col,  g_col);

    cudaFuncSetAttribute(gemm2_db_kernel,
                         cudaFuncAttributeMaxDynamicSharedMemorySize, G2_SMEM_TOT);

    const int TB = 256;

    // ===== CSR build (graph shared by both layers) =====
    cudaMemsetAsync(deg, 0, N_NODES * sizeof(int));
    hist_kernel<<<(ET + TB - 1) / TB, TB>>>(ei, E, ET, deg);
    scan_kernel<<<1, 1024>>>(deg, rowp, curs);
    scatter_kernel<<<(ET + TB - 1) / TB, TB>>>(ei, E, ET, curs, col);

    // ===== layer 1 (H=4, F=256) =====
    gemm1_kernel<<<(N_NODES + 63) / 64, TB>>>(x, W1, h1);
    scores_kernel<H1><<<(N_NODES * H1 * 32 + TB - 1) / TB, TB>>>(h1, a_src1, a_dst1, ss, sd);
    edge_agg_csr<H1, F1><<<(N_NODES * 32 + TB - 1) / TB, TB>>>(rowp, deg, col, ss, sd, z, h1, agg1);

    // ===== layer 2: f32x2 gemm2 fusing layer-1 normalize+bias+elu =====
    gemm2_db_kernel<<<(N_NODES + 127) / 128, TB, G2_SMEM_TOT>>>(agg1, z, b1, W2, h2);
    scores_kernel<H2><<<(N_NODES * H2 * 32 + TB - 1) / TB, TB>>>(h2, a_src2, a_dst2, ss, sd);
    edge_agg_csr<H2, F2><<<(N_NODES * 32 + TB - 1) / TB, TB>>>(rowp, deg, col, ss, sd, z, h2, agg2);

    // ===== final: fuses layer-2 normalize+bias+elu with the 128->1 dot =====
    out_fused_kernel<<<(N_NODES * 32 + TB - 1) / TB, TB>>>(agg2, z, b2, Wfc, bfc, out);
}